// round 13
// baseline (speedup 1.0000x reference)
#include <cuda_runtime.h>
#include <cuda_bf16.h>
#include <cstdint>

#define NV    8192
#define DD    256
#define TM    128
#define NT    64
#define NPAIR (NT * (NT + 1) / 2)   // 2080 upper-tri tiles
#define POOLE 4096

// Scratch (static device globals — allocation-free)
__device__ uint32_t g_edges[POOLE];  // packed (i<<13)|j, i<j
__device__ int      g_nedges;
__device__ float    g_thr;
__device__ __nv_bfloat16 g_s0[NV * DD];   // bf16 split: V = s0 + s1 + s2
__device__ __nv_bfloat16 g_s1[NV * DD];
__device__ __nv_bfloat16 g_s2[NV * DD];

// ---------------------------------------------------------------------------
__device__ __forceinline__ uint32_t smem_u32(const void* p) {
    uint32_t a;
    asm("{ .reg .u64 t; cvta.to.shared.u64 t, %1; cvt.u32.u64 %0, t; }"
        : "=r"(a) : "l"(p));
    return a;
}
__device__ __forceinline__ uint32_t sw128(uint32_t off) {
    return off ^ ((off >> 3) & 0x70u);
}

#define LDSM_X4(r0, r1, r2, r3, addr) \
    asm volatile("ldmatrix.sync.aligned.m8n8.x4.shared.b16 {%0,%1,%2,%3}, [%4];" \
                 : "=r"(r0), "=r"(r1), "=r"(r2), "=r"(r3) : "r"(addr))

#define MMA16816(c0, c1, c2, c3, a0, a1, a2, a3, b0, b1) \
    asm volatile("mma.sync.aligned.m16n8k16.row.col.f32.bf16.bf16.f32 " \
                 "{%0,%1,%2,%3}, {%4,%5,%6,%7}, {%8,%9}, {%0,%1,%2,%3};" \
                 : "+f"(c0), "+f"(c1), "+f"(c2), "+f"(c3) \
                 : "r"(a0), "r"(a1), "r"(a2), "r"(a3), "r"(b0), "r"(b1))

#define CP_ASYNC16(dst, src) \
    asm volatile("cp.async.cg.shared.global [%0], [%1], 16;" \
                 :: "r"(dst), "l"(src) : "memory")

// ---------------------------------------------------------------------------
// Kernel A: resolve threshold by value range; reset edge counter.
// ---------------------------------------------------------------------------
__global__ void pick_thr_kernel(const void* c0, const void* c1, const void* c2) {
    float t = 0.25f;
    const void* cands[3] = {c0, c1, c2};
#pragma unroll
    for (int i = 0; i < 3; i++) {
        if (cands[i] != nullptr) {
            const float v = *(const float*)cands[i];
            if (v >= 0.001f && v <= 0.999f) { t = v; break; }
        }
    }
    g_thr = t;
    g_nedges = 0;
}

// ---------------------------------------------------------------------------
// Kernel B: 3-way bf16 split of V (fp32-exact decomposition).
// ---------------------------------------------------------------------------
__global__ __launch_bounds__(256) void split_kernel(const float* __restrict__ V) {
    const int i = blockIdx.x * blockDim.x + threadIdx.x;
    if (i < NV * DD) {
        const float x = V[i];
        const __nv_bfloat16 b0 = __float2bfloat16_rn(x);
        const float r1 = x - __bfloat162float(b0);
        const __nv_bfloat16 b1 = __float2bfloat16_rn(r1);
        const float r2 = r1 - __bfloat162float(b1);
        const __nv_bfloat16 b2 = __float2bfloat16_rn(r2);
        g_s0[i] = b0; g_s1[i] = b1; g_s2[i] = b2;
    }
}

// ---------------------------------------------------------------------------
// Kernel 1: mma.sync bf16 GEMM with 6-term split, cp.async double-buffered.
// 1-D grid over 2080 upper-tri tiles. 128x128 tile, 8 warps (64x32 warptile),
// K streamed in 8 chunks of 32. Per stage: 3 tile-pairs of 128B rows:
//   P0 = [A0|A1], P1 = [A2|B0], P2 = [B1|B2]   (48 KB/stage, 2 stages)
// Per k16 step: 6 B-LDSM + 12 A-LDSM feed 96 MMAs.
// ---------------------------------------------------------------------------
#define OFFR(r) ((r) * NT - (r) * ((r) - 1) / 2)

__global__ __launch_bounds__(256, 2) void simgemm_tc() {
    // decode linear block id -> (ti, tj), ti <= tj
    const int x = blockIdx.x;
    int ti = (int)(NT + 0.5f - sqrtf((NT + 0.5f) * (NT + 0.5f) - 2.0f * (float)x));
    if (ti < 0) ti = 0;
    while (OFFR(ti + 1) <= x) ++ti;
    while (OFFR(ti) > x) --ti;
    const int tj = ti + (x - OFFR(ti));

    __shared__ __align__(1024) char sb[2][3 * 16384];

    const int tid = threadIdx.x;
    const int wid = tid >> 5, lid = tid & 31;
    const int m_base = (wid & 1) * 64;
    const int n_base = (wid >> 1) * 32;

    // split-matrix pointers per (pair, half)
    const size_t arow = (size_t)ti * TM * DD;
    const size_t brow = (size_t)tj * TM * DD;
    const __nv_bfloat16* msel[3][2] = {
        { g_s0 + arow, g_s1 + arow },   // P0: A0 | A1
        { g_s2 + arow, g_s0 + brow },   // P1: A2 | B0
        { g_s1 + brow, g_s2 + brow }    // P2: B1 | B2
    };

    const uint32_t sb0 = smem_u32(sb[0]);
    const uint32_t sb1 = smem_u32(sb[1]);

    float acc[4][4][4];
#pragma unroll
    for (int mf = 0; mf < 4; mf++)
#pragma unroll
        for (int nf = 0; nf < 4; nf++)
#pragma unroll
            for (int r = 0; r < 4; r++) acc[mf][nf][r] = 0.0f;

    // ---- async stage loader: 3072 16B chunks / 256 threads = 12 each
#define LOAD_STAGE(stbase, kc)                                                 \
    do {                                                                       \
        _Pragma("unroll")                                                      \
        for (int c = 0; c < 12; ++c) {                                         \
            const int idx = c * 256 + tid;                                     \
            const int T = idx >> 10, q = idx & 1023;                           \
            const int row = q >> 3, c8 = q & 7;                                \
            const int h = c8 >> 2, c4 = c8 & 3;                                \
            const __nv_bfloat16* src = msel[T][h] + (size_t)row * DD           \
                                     + (kc) * 32 + c4 * 8;                     \
            const uint32_t dst = (stbase) + T * 16384                          \
                               + sw128((uint32_t)(row * 128 + c8 * 16));       \
            CP_ASYNC16(dst, src);                                              \
        }                                                                      \
        asm volatile("cp.async.commit_group;" ::: "memory");                   \
    } while (0)

    LOAD_STAGE(sb0, 0);

    const int BP[3] = {1, 2, 2}, BH[3] = {1, 0, 1};   // B split s -> (pair, half)
    const int AP[3] = {0, 0, 1}, AH[3] = {0, 1, 0};   // A split s -> (pair, half)
    const int TAc[6] = {0, 0, 1, 1, 0, 2};
    const int TBc[6] = {0, 1, 0, 1, 2, 0};

#pragma unroll 1
    for (int kc = 0; kc < 8; ++kc) {
        if (kc < 7) {
            LOAD_STAGE((kc & 1) ? sb0 : sb1, kc + 1);
            asm volatile("cp.async.wait_group 1;" ::: "memory");
        } else {
            asm volatile("cp.async.wait_group 0;" ::: "memory");
        }
        __syncthreads();

        const uint32_t base = (kc & 1) ? sb1 : sb0;
#pragma unroll
        for (int ks = 0; ks < 2; ++ks) {
            // B frags: 3 splits x 2 k-halves x 4 nf
            uint32_t b[3][2][4];
#pragma unroll
            for (int s = 0; s < 3; ++s) {
                const uint32_t rowb = (uint32_t)(n_base + lid);
                const uint32_t col0 = (uint32_t)(BH[s] * 64 + ks * 32);
                LDSM_X4(b[s][0][0], b[s][0][1], b[s][0][2], b[s][0][3],
                        base + BP[s] * 16384 + sw128(rowb * 128 + col0));
                LDSM_X4(b[s][1][0], b[s][1][1], b[s][1][2], b[s][1][3],
                        base + BP[s] * 16384 + sw128(rowb * 128 + col0 + 16));
            }
#pragma unroll
            for (int mf = 0; mf < 4; ++mf) {
                uint32_t a[3][4];
                const uint32_t rowa = (uint32_t)(m_base + mf * 16 + (lid & 15));
#pragma unroll
                for (int s = 0; s < 3; ++s) {
                    const uint32_t col = (uint32_t)(AH[s] * 64 + ks * 32 + ((lid >> 4) << 4));
                    LDSM_X4(a[s][0], a[s][1], a[s][2], a[s][3],
                            base + AP[s] * 16384 + sw128(rowa * 128 + col));
                }
#pragma unroll
                for (int t6 = 0; t6 < 6; ++t6) {
                    const int sa = TAc[t6], sbx = TBc[t6];
#pragma unroll
                    for (int nf = 0; nf < 4; ++nf) {
                        MMA16816(acc[mf][nf][0], acc[mf][nf][1],
                                 acc[mf][nf][2], acc[mf][nf][3],
                                 a[sa][0], a[sa][1], a[sa][2], a[sa][3],
                                 b[sbx][0][nf], b[sbx][1][nf]);
                    }
                }
            }
        }
        __syncthreads();
    }

    // ---- epilogue: threshold, append edges (i<j) — mapping validated R12
    const float thr = g_thr;
    const int gi0 = ti * TM + m_base + (lid >> 2);
    const int gj0 = tj * TM + n_base + (lid & 3) * 2;
#pragma unroll
    for (int mf = 0; mf < 4; ++mf)
#pragma unroll
        for (int nf = 0; nf < 4; ++nf)
#pragma unroll
            for (int r = 0; r < 4; ++r) {
                if (acc[mf][nf][r] >= thr) {
                    const int i = gi0 + mf * 16 + ((r >> 1) << 3);
                    const int j = gj0 + nf * 8 + (r & 1);
                    if (i < j) {
                        const int pos = atomicAdd(&g_nedges, 1);
                        if (pos < POOLE)
                            g_edges[pos] = ((uint32_t)i << 13) | (uint32_t)j;
                    }
                }
            }
}

// ---------------------------------------------------------------------------
// Kernel 2: exact merge. Sort edges; parallel min-label CC; then ONE leader
// thread per component replays its edges in ascending order with the
// class(i)-wins DSU (validated exact in round 10). Components are disjoint in
// parent[], so leaders run concurrently.
// ---------------------------------------------------------------------------
__global__ __launch_bounds__(1024) void merge_kernel(float* __restrict__ out) {
    __shared__ unsigned short parent[NV];   // 16 KB
    __shared__ uint32_t comp[NV];           // 32 KB
    __shared__ uint32_t pool[POOLE];        // 16 KB
    __shared__ uint32_t touched[NV / 32];   // 1 KB
    __shared__ int sE, s_changed;

    const int t = threadIdx.x;
    for (int m = t; m < NV; m += 1024) { parent[m] = (unsigned short)m; comp[m] = (uint32_t)m; }
    for (int m = t; m < NV / 32; m += 1024) touched[m] = 0u;
    if (t == 0) {
        const int e = g_nedges;
        sE = (e < POOLE) ? e : POOLE;
    }
    __syncthreads();
    const int E = sE;
    for (int e = t; e < POOLE; e += 1024)
        pool[e] = (e < E) ? g_edges[e] : 0xFFFFFFFFu;
    __syncthreads();

    // mark touched vertices
    for (int e = t; e < E; e += 1024) {
        const uint32_t p = pool[e];
        const int i = (int)(p >> 13), j = (int)(p & 8191u);
        atomicOr(&touched[i >> 5], 1u << (i & 31));
        atomicOr(&touched[j >> 5], 1u << (j & 31));
    }

    // bitonic sort (ascending)
    for (int k = 2; k <= POOLE; k <<= 1) {
        for (int j = k >> 1; j > 0; j >>= 1) {
            __syncthreads();
            for (int idx = t; idx < POOLE; idx += 1024) {
                const int l = idx ^ j;
                if (l > idx) {
                    const uint32_t a = pool[idx], b = pool[l];
                    const bool up = ((idx & k) == 0);
                    if ((a > b) == up) { pool[idx] = b; pool[l] = a; }
                }
            }
        }
    }
    __syncthreads();

    // parallel connected components: min-label hooking + pointer jumping
    for (int iter = 0; iter < 64; ++iter) {
        if (t == 0) s_changed = 0;
        __syncthreads();
        for (int e = t; e < E; e += 1024) {
            const uint32_t p = pool[e];
            const int i = (int)(p >> 13), j = (int)(p & 8191u);
            const uint32_t a = comp[i], b = comp[j];
            if (a != b) {
                const uint32_t lo = (a < b) ? a : b;
                if (a > lo) atomicMin(&comp[i], lo);
                if (b > lo) atomicMin(&comp[j], lo);
                s_changed = 1;
            }
        }
        __syncthreads();
        if (!s_changed) break;
#pragma unroll
        for (int r = 0; r < 3; ++r) {
            for (int v = t; v < NV; v += 1024)
                atomicMin(&comp[v], comp[comp[v]]);
            __syncthreads();
        }
    }
    __syncthreads();

    // per-component sequential replay (leaders in parallel)
    for (int v = t; v < NV; v += 1024) {
        const bool leader = (comp[v] == (uint32_t)v) &&
                            ((touched[v >> 5] >> (v & 31)) & 1u);
        if (leader) {
            for (int e = 0; e < E; ++e) {
                const uint32_t p = pool[e];
                const int i = (int)(p >> 13);
                if (comp[i] != (uint32_t)v) continue;
                const int j = (int)(p & 8191u);
                int ri = i;
                while (true) { const int q = parent[ri]; if (q == ri) break; ri = q; }
                int rj = j;
                while (true) { const int q = parent[rj]; if (q == rj) break; rj = q; }
                if (ri != rj) parent[rj] = (unsigned short)ri;
                parent[i] = (unsigned short)ri;   // path compression
                parent[j] = (unsigned short)ri;
            }
        }
    }
    __syncthreads();

    // final find + float writeback
    for (int m = t; m < NV; m += 1024) {
        int r = m;
        while (true) { const int q = parent[r]; if (q == r) break; r = q; }
        out[m] = (float)r;
    }
}

// ---------------------------------------------------------------------------
extern "C" void kernel_launch(void* const* d_in, const int* in_sizes, int n_in,
                              void* d_out, int out_size) {
    // V = the LARGEST input; other inputs are threshold candidates.
    int vi = 0;
    for (int i = 1; i < n_in; i++)
        if (in_sizes[i] > in_sizes[vi]) vi = i;
    const float* V = (const float*)d_in[vi];

    const void* cands[3] = {nullptr, nullptr, nullptr};
    int nc = 0;
    for (int i = 0; i < n_in && nc < 3; i++)
        if (i != vi) cands[nc++] = d_in[i];

    float* out = (float*)d_out;

    pick_thr_kernel<<<1, 1>>>(cands[0], cands[1], cands[2]);
    split_kernel<<<(NV * DD + 255) / 256, 256>>>(V);
    simgemm_tc<<<NPAIR, 256>>>();
    merge_kernel<<<1, 1024>>>(out);
}

// round 14
// speedup vs baseline: 2.2968x; 2.2968x over previous
#include <cuda_runtime.h>
#include <cuda_bf16.h>
#include <cstdint>

#define NV    8192
#define DD    256
#define TM    128
#define NT    64
#define NPAIR (NT * (NT + 1) / 2)   // 2080 upper-tri tiles
#define POOLE 4096

// Scratch (static device globals — allocation-free)
__device__ uint32_t g_edges[POOLE];  // packed (i<<13)|j, i<j
__device__ int      g_nedges;
__device__ float    g_thr;
__device__ __nv_bfloat16 g_s0[NV * DD];   // bf16 split: V = s0 + s1 + s2
__device__ __nv_bfloat16 g_s1[NV * DD];
__device__ __nv_bfloat16 g_s2[NV * DD];

// ---------------------------------------------------------------------------
__device__ __forceinline__ uint32_t smem_u32(const void* p) {
    uint32_t a;
    asm("{ .reg .u64 t; cvta.to.shared.u64 t, %1; cvt.u32.u64 %0, t; }"
        : "=r"(a) : "l"(p));
    return a;
}
__device__ __forceinline__ uint32_t sw128(uint32_t off) {
    return off ^ ((off >> 3) & 0x70u);
}

#define LDSM_X4(r0, r1, r2, r3, addr) \
    asm volatile("ldmatrix.sync.aligned.m8n8.x4.shared.b16 {%0,%1,%2,%3}, [%4];" \
                 : "=r"(r0), "=r"(r1), "=r"(r2), "=r"(r3) : "r"(addr))

#define MMA16816(c0, c1, c2, c3, a0, a1, a2, a3, b0, b1) \
    asm volatile("mma.sync.aligned.m16n8k16.row.col.f32.bf16.bf16.f32 " \
                 "{%0,%1,%2,%3}, {%4,%5,%6,%7}, {%8,%9}, {%0,%1,%2,%3};" \
                 : "+f"(c0), "+f"(c1), "+f"(c2), "+f"(c3) \
                 : "r"(a0), "r"(a1), "r"(a2), "r"(a3), "r"(b0), "r"(b1))

#define CP_ASYNC16(dst, src) \
    asm volatile("cp.async.cg.shared.global [%0], [%1], 16;" \
                 :: "r"(dst), "l"(src) : "memory")

// ---------------------------------------------------------------------------
// Kernel A: resolve threshold by value range; reset edge counter.
// ---------------------------------------------------------------------------
__global__ void pick_thr_kernel(const void* c0, const void* c1, const void* c2) {
    float t = 0.25f;
    const void* cands[3] = {c0, c1, c2};
#pragma unroll
    for (int i = 0; i < 3; i++) {
        if (cands[i] != nullptr) {
            const float v = *(const float*)cands[i];
            if (v >= 0.001f && v <= 0.999f) { t = v; break; }
        }
    }
    g_thr = t;
    g_nedges = 0;
}

// ---------------------------------------------------------------------------
// Kernel B: 3-way bf16 split of V (fp32-exact decomposition).
// ---------------------------------------------------------------------------
__global__ __launch_bounds__(256) void split_kernel(const float* __restrict__ V) {
    const int i = blockIdx.x * blockDim.x + threadIdx.x;
    if (i < NV * DD) {
        const float x = V[i];
        const __nv_bfloat16 b0 = __float2bfloat16_rn(x);
        const float r1 = x - __bfloat162float(b0);
        const __nv_bfloat16 b1 = __float2bfloat16_rn(r1);
        const float r2 = r1 - __bfloat162float(b1);
        const __nv_bfloat16 b2 = __float2bfloat16_rn(r2);
        g_s0[i] = b0; g_s1[i] = b1; g_s2[i] = b2;
    }
}

// ---------------------------------------------------------------------------
// Kernel 1: mma.sync bf16 GEMM with 6-term split, cp.async double-buffered.
// (unchanged from round 13 — measured ~250 us)
// ---------------------------------------------------------------------------
#define OFFR(r) ((r) * NT - (r) * ((r) - 1) / 2)

__global__ __launch_bounds__(256, 2) void simgemm_tc() {
    const int x = blockIdx.x;
    int ti = (int)(NT + 0.5f - sqrtf((NT + 0.5f) * (NT + 0.5f) - 2.0f * (float)x));
    if (ti < 0) ti = 0;
    while (OFFR(ti + 1) <= x) ++ti;
    while (OFFR(ti) > x) --ti;
    const int tj = ti + (x - OFFR(ti));

    __shared__ __align__(1024) char sb[2][3 * 16384];

    const int tid = threadIdx.x;
    const int wid = tid >> 5, lid = tid & 31;
    const int m_base = (wid & 1) * 64;
    const int n_base = (wid >> 1) * 32;

    const size_t arow = (size_t)ti * TM * DD;
    const size_t brow = (size_t)tj * TM * DD;
    const __nv_bfloat16* msel[3][2] = {
        { g_s0 + arow, g_s1 + arow },   // P0: A0 | A1
        { g_s2 + arow, g_s0 + brow },   // P1: A2 | B0
        { g_s1 + brow, g_s2 + brow }    // P2: B1 | B2
    };

    const uint32_t sb0 = smem_u32(sb[0]);
    const uint32_t sb1 = smem_u32(sb[1]);

    float acc[4][4][4];
#pragma unroll
    for (int mf = 0; mf < 4; mf++)
#pragma unroll
        for (int nf = 0; nf < 4; nf++)
#pragma unroll
            for (int r = 0; r < 4; r++) acc[mf][nf][r] = 0.0f;

#define LOAD_STAGE(stbase, kc)                                                 \
    do {                                                                       \
        _Pragma("unroll")                                                      \
        for (int c = 0; c < 12; ++c) {                                         \
            const int idx = c * 256 + tid;                                     \
            const int T = idx >> 10, q = idx & 1023;                           \
            const int row = q >> 3, c8 = q & 7;                                \
            const int h = c8 >> 2, c4 = c8 & 3;                                \
            const __nv_bfloat16* src = msel[T][h] + (size_t)row * DD           \
                                     + (kc) * 32 + c4 * 8;                     \
            const uint32_t dst = (stbase) + T * 16384                          \
                               + sw128((uint32_t)(row * 128 + c8 * 16));       \
            CP_ASYNC16(dst, src);                                              \
        }                                                                      \
        asm volatile("cp.async.commit_group;" ::: "memory");                   \
    } while (0)

    LOAD_STAGE(sb0, 0);

    const int BP[3] = {1, 2, 2}, BH[3] = {1, 0, 1};
    const int AP[3] = {0, 0, 1}, AH[3] = {0, 1, 0};
    const int TAc[6] = {0, 0, 1, 1, 0, 2};
    const int TBc[6] = {0, 1, 0, 1, 2, 0};

#pragma unroll 1
    for (int kc = 0; kc < 8; ++kc) {
        if (kc < 7) {
            LOAD_STAGE((kc & 1) ? sb0 : sb1, kc + 1);
            asm volatile("cp.async.wait_group 1;" ::: "memory");
        } else {
            asm volatile("cp.async.wait_group 0;" ::: "memory");
        }
        __syncthreads();

        const uint32_t base = (kc & 1) ? sb1 : sb0;
#pragma unroll
        for (int ks = 0; ks < 2; ++ks) {
            uint32_t b[3][2][4];
#pragma unroll
            for (int s = 0; s < 3; ++s) {
                const uint32_t rowb = (uint32_t)(n_base + lid);
                const uint32_t col0 = (uint32_t)(BH[s] * 64 + ks * 32);
                LDSM_X4(b[s][0][0], b[s][0][1], b[s][0][2], b[s][0][3],
                        base + BP[s] * 16384 + sw128(rowb * 128 + col0));
                LDSM_X4(b[s][1][0], b[s][1][1], b[s][1][2], b[s][1][3],
                        base + BP[s] * 16384 + sw128(rowb * 128 + col0 + 16));
            }
#pragma unroll
            for (int mf = 0; mf < 4; ++mf) {
                uint32_t a[3][4];
                const uint32_t rowa = (uint32_t)(m_base + mf * 16 + (lid & 15));
#pragma unroll
                for (int s = 0; s < 3; ++s) {
                    const uint32_t col = (uint32_t)(AH[s] * 64 + ks * 32 + ((lid >> 4) << 4));
                    LDSM_X4(a[s][0], a[s][1], a[s][2], a[s][3],
                            base + AP[s] * 16384 + sw128(rowa * 128 + col));
                }
#pragma unroll
                for (int t6 = 0; t6 < 6; ++t6) {
                    const int sa = TAc[t6], sbx = TBc[t6];
#pragma unroll
                    for (int nf = 0; nf < 4; ++nf) {
                        MMA16816(acc[mf][nf][0], acc[mf][nf][1],
                                 acc[mf][nf][2], acc[mf][nf][3],
                                 a[sa][0], a[sa][1], a[sa][2], a[sa][3],
                                 b[sbx][0][nf], b[sbx][1][nf]);
                    }
                }
            }
        }
        __syncthreads();
    }

    const float thr = g_thr;
    const int gi0 = ti * TM + m_base + (lid >> 2);
    const int gj0 = tj * TM + n_base + (lid & 3) * 2;
#pragma unroll
    for (int mf = 0; mf < 4; ++mf)
#pragma unroll
        for (int nf = 0; nf < 4; ++nf)
#pragma unroll
            for (int r = 0; r < 4; ++r) {
                if (acc[mf][nf][r] >= thr) {
                    const int i = gi0 + mf * 16 + ((r >> 1) << 3);
                    const int j = gj0 + nf * 8 + (r & 1);
                    if (i < j) {
                        const int pos = atomicAdd(&g_nedges, 1);
                        if (pos < POOLE)
                            g_edges[pos] = ((uint32_t)i << 13) | (uint32_t)j;
                    }
                }
            }
}

// ---------------------------------------------------------------------------
// Kernel 2: exact merge, segmented replay.
// 1) parallel CC (atomicMin hooking + pointer jumping) -> comp[v] = component
//    min-vertex; 2) sort u64 keys (comp<<26)|(i<<13)|j -> edges grouped by
//    component, ascending (i,j) within each (= reference replay order, since
//    components never interact); 3) each leader replays ONLY its contiguous
//    segment with the class(i)-wins DSU (validated exact in round 10).
// ---------------------------------------------------------------------------
__global__ __launch_bounds__(1024) void merge_kernel(float* __restrict__ out) {
    __shared__ unsigned short parent[NV];            // 16 KB
    __shared__ uint32_t comp[NV];                    // 32 KB
    __shared__ uint32_t e32[POOLE];                  // 16 KB
    __shared__ unsigned long long pool[POOLE];       // 32 KB
    __shared__ unsigned short comp_start[NV];        // 16 KB
    __shared__ int sE, s_changed;

    const int t = threadIdx.x;
    for (int m = t; m < NV; m += 1024) {
        parent[m] = (unsigned short)m;
        comp[m] = (uint32_t)m;
        comp_start[m] = 0xFFFFu;
    }
    if (t == 0) {
        const int e = g_nedges;
        sE = (e < POOLE) ? e : POOLE;
    }
    __syncthreads();
    const int E = sE;
    for (int e = t; e < POOLE; e += 1024)
        e32[e] = (e < E) ? g_edges[e] : 0xFFFFFFFFu;
    __syncthreads();

    // ---- parallel connected components: min-label hooking + pointer jumping
    for (int iter = 0; iter < 64; ++iter) {
        if (t == 0) s_changed = 0;
        __syncthreads();
        for (int e = t; e < E; e += 1024) {
            const uint32_t p = e32[e];
            const int i = (int)(p >> 13), j = (int)(p & 8191u);
            const uint32_t a = comp[i], b = comp[j];
            if (a != b) {
                const uint32_t lo = (a < b) ? a : b;
                if (a > lo) atomicMin(&comp[i], lo);
                if (b > lo) atomicMin(&comp[j], lo);
                s_changed = 1;
            }
        }
        __syncthreads();
        if (!s_changed) break;
#pragma unroll
        for (int r = 0; r < 3; ++r) {
            for (int v = t; v < NV; v += 1024)
                atomicMin(&comp[v], comp[comp[v]]);
            __syncthreads();
        }
    }
    __syncthreads();

    // ---- build u64 keys: (comp << 26) | edge ; pad with all-ones
    for (int e = t; e < POOLE; e += 1024) {
        if (e < E) {
            const uint32_t p = e32[e];
            pool[e] = ((unsigned long long)comp[p >> 13] << 26) | (unsigned long long)p;
        } else {
            pool[e] = ~0ULL;
        }
    }
    __syncthreads();

    // ---- bitonic sort (ascending)
    for (int k = 2; k <= POOLE; k <<= 1) {
        for (int j = k >> 1; j > 0; j >>= 1) {
            for (int idx = t; idx < POOLE; idx += 1024) {
                const int l = idx ^ j;
                if (l > idx) {
                    const unsigned long long a = pool[idx], b = pool[l];
                    const bool up = ((idx & k) == 0);
                    if ((a > b) == up) { pool[idx] = b; pool[l] = a; }
                }
            }
            __syncthreads();
        }
    }

    // ---- segment starts per component
    for (int e = t; e < E; e += 1024) {
        const uint32_t c = (uint32_t)(pool[e] >> 26);
        if (e == 0 || (uint32_t)(pool[e - 1] >> 26) != c)
            comp_start[c] = (unsigned short)e;
    }
    __syncthreads();

    // ---- per-component sequential replay (leaders concurrent, segments only)
    for (int v = t; v < NV; v += 1024) {
        if (comp[v] == (uint32_t)v && comp_start[v] != 0xFFFFu) {
            int e = comp_start[v];
            while (e < E && (uint32_t)(pool[e] >> 26) == (uint32_t)v) {
                const uint32_t p = (uint32_t)(pool[e] & 0x3FFFFFFull);
                const int i = (int)(p >> 13);
                const int j = (int)(p & 8191u);
                int ri = i;
                while (true) { const int q = parent[ri]; if (q == ri) break; ri = q; }
                int rj = j;
                while (true) { const int q = parent[rj]; if (q == rj) break; rj = q; }
                if (ri != rj) parent[rj] = (unsigned short)ri;
                parent[i] = (unsigned short)ri;   // path compression
                parent[j] = (unsigned short)ri;
                ++e;
            }
        }
    }
    __syncthreads();

    // ---- final find + float writeback
    for (int m = t; m < NV; m += 1024) {
        int r = m;
        while (true) { const int q = parent[r]; if (q == r) break; r = q; }
        out[m] = (float)r;
    }
}

// ---------------------------------------------------------------------------
extern "C" void kernel_launch(void* const* d_in, const int* in_sizes, int n_in,
                              void* d_out, int out_size) {
    // V = the LARGEST input; other inputs are threshold candidates.
    int vi = 0;
    for (int i = 1; i < n_in; i++)
        if (in_sizes[i] > in_sizes[vi]) vi = i;
    const float* V = (const float*)d_in[vi];

    const void* cands[3] = {nullptr, nullptr, nullptr};
    int nc = 0;
    for (int i = 0; i < n_in && nc < 3; i++)
        if (i != vi) cands[nc++] = d_in[i];

    float* out = (float*)d_out;

    pick_thr_kernel<<<1, 1>>>(cands[0], cands[1], cands[2]);
    split_kernel<<<(NV * DD + 255) / 256, 256>>>(V);
    simgemm_tc<<<NPAIR, 256>>>();
    merge_kernel<<<1, 1024>>>(out);
}

// round 15
// speedup vs baseline: 5.6578x; 2.4633x over previous
#include <cuda_runtime.h>
#include <cuda_bf16.h>
#include <cstdint>

#define NV    8192
#define DD    256
#define TM    128
#define NT    64
#define NPAIR (NT * (NT + 1) / 2)   // 2080 upper-tri tiles
#define POOLE 4096
#define BANDC 16384                  // band pool (expected ~700; 20x margin)
#define MARG  0.0045f                // certified bf16 1-term error bound +slack

// Scratch (static device globals — allocation-free)
__device__ uint32_t g_edges[POOLE];  // packed (i<<13)|j, i<j
__device__ int      g_nedges;
__device__ uint32_t g_band[BANDC];   // pairs needing exact recheck
__device__ int      g_nband;
__device__ float    g_thr;
__device__ __nv_bfloat16 g_s0[NV * DD];   // bf16 head of V

// ---------------------------------------------------------------------------
__device__ __forceinline__ uint32_t smem_u32(const void* p) {
    uint32_t a;
    asm("{ .reg .u64 t; cvta.to.shared.u64 t, %1; cvt.u32.u64 %0, t; }"
        : "=r"(a) : "l"(p));
    return a;
}
__device__ __forceinline__ uint32_t sw128(uint32_t off) {
    return off ^ ((off >> 3) & 0x70u);
}

#define LDSM_X4(r0, r1, r2, r3, addr) \
    asm volatile("ldmatrix.sync.aligned.m8n8.x4.shared.b16 {%0,%1,%2,%3}, [%4];" \
                 : "=r"(r0), "=r"(r1), "=r"(r2), "=r"(r3) : "r"(addr))

#define MMA16816(c0, c1, c2, c3, a0, a1, a2, a3, b0, b1) \
    asm volatile("mma.sync.aligned.m16n8k16.row.col.f32.bf16.bf16.f32 " \
                 "{%0,%1,%2,%3}, {%4,%5,%6,%7}, {%8,%9}, {%0,%1,%2,%3};" \
                 : "+f"(c0), "+f"(c1), "+f"(c2), "+f"(c3) \
                 : "r"(a0), "r"(a1), "r"(a2), "r"(a3), "r"(b0), "r"(b1))

#define CP_ASYNC16(dst, src) \
    asm volatile("cp.async.cg.shared.global [%0], [%1], 16;" \
                 :: "r"(dst), "l"(src) : "memory")

// ---------------------------------------------------------------------------
// Kernel A: resolve threshold by value range; reset counters.
// ---------------------------------------------------------------------------
__global__ void pick_thr_kernel(const void* c0, const void* c1, const void* c2) {
    float t = 0.25f;
    const void* cands[3] = {c0, c1, c2};
#pragma unroll
    for (int i = 0; i < 3; i++) {
        if (cands[i] != nullptr) {
            const float v = *(const float*)cands[i];
            if (v >= 0.001f && v <= 0.999f) { t = v; break; }
        }
    }
    g_thr = t;
    g_nedges = 0;
    g_nband  = 0;
}

// ---------------------------------------------------------------------------
// Kernel B: bf16 head of V (1-term prefilter operand).
// ---------------------------------------------------------------------------
__global__ __launch_bounds__(256) void split_kernel(const float* __restrict__ V) {
    const int i = blockIdx.x * blockDim.x + threadIdx.x;
    if (i < NV * DD) g_s0[i] = __float2bfloat16_rn(V[i]);
}

// ---------------------------------------------------------------------------
// Kernel 1: 1-term bf16 prefilter GEMM (cp.async double-buffered, BK=32).
// approx >= thr+MARG -> certain edge; in [thr-MARG, thr+MARG) -> band;
// else certain non-edge. Certified: |approx - exact| < 0.0040 < MARG.
// ---------------------------------------------------------------------------
#define OFFR(r) ((r) * NT - (r) * ((r) - 1) / 2)

__global__ __launch_bounds__(256, 2) void simgemm_tc() {
    const int x = blockIdx.x;
    int ti = (int)(NT + 0.5f - sqrtf((NT + 0.5f) * (NT + 0.5f) - 2.0f * (float)x));
    if (ti < 0) ti = 0;
    while (OFFR(ti + 1) <= x) ++ti;
    while (OFFR(ti) > x) --ti;
    const int tj = ti + (x - OFFR(ti));

    __shared__ __align__(1024) char sb[2][16384];   // [A0 | B0] per stage

    const int tid = threadIdx.x;
    const int wid = tid >> 5, lid = tid & 31;
    const int m_base = (wid & 1) * 64;
    const int n_base = (wid >> 1) * 32;

    const __nv_bfloat16* Ap = g_s0 + (size_t)ti * TM * DD;
    const __nv_bfloat16* Bp = g_s0 + (size_t)tj * TM * DD;

    const uint32_t sb0 = smem_u32(sb[0]);
    const uint32_t sb1 = smem_u32(sb[1]);

    float acc[4][4][4];
#pragma unroll
    for (int mf = 0; mf < 4; mf++)
#pragma unroll
        for (int nf = 0; nf < 4; nf++)
#pragma unroll
            for (int r = 0; r < 4; r++) acc[mf][nf][r] = 0.0f;

    // stage loader: 1024 16B chunks / 256 threads = 4 each
#define LOAD_STAGE(stbase, kc)                                                 \
    do {                                                                       \
        _Pragma("unroll")                                                      \
        for (int c = 0; c < 4; ++c) {                                          \
            const int q = c * 256 + tid;                                       \
            const int row = q >> 3, c8 = q & 7;                                \
            const int h = c8 >> 2, c4 = c8 & 3;                                \
            const __nv_bfloat16* src = (h ? Bp : Ap) + (size_t)row * DD        \
                                     + (kc) * 32 + c4 * 8;                     \
            const uint32_t dst = (stbase)                                      \
                               + sw128((uint32_t)(row * 128 + c8 * 16));       \
            CP_ASYNC16(dst, src);                                              \
        }                                                                      \
        asm volatile("cp.async.commit_group;" ::: "memory");                   \
    } while (0)

    LOAD_STAGE(sb0, 0);

#pragma unroll 1
    for (int kc = 0; kc < 8; ++kc) {
        if (kc < 7) {
            LOAD_STAGE((kc & 1) ? sb0 : sb1, kc + 1);
            asm volatile("cp.async.wait_group 1;" ::: "memory");
        } else {
            asm volatile("cp.async.wait_group 0;" ::: "memory");
        }
        __syncthreads();

        const uint32_t base = (kc & 1) ? sb1 : sb0;
#pragma unroll
        for (int ks = 0; ks < 2; ++ks) {
            uint32_t b[2][4];
            {
                const uint32_t rowb = (uint32_t)(n_base + lid);
                const uint32_t col0 = (uint32_t)(64 + ks * 32);   // B half
                LDSM_X4(b[0][0], b[0][1], b[0][2], b[0][3],
                        base + sw128(rowb * 128 + col0));
                LDSM_X4(b[1][0], b[1][1], b[1][2], b[1][3],
                        base + sw128(rowb * 128 + col0 + 16));
            }
#pragma unroll
            for (int mf = 0; mf < 4; ++mf) {
                uint32_t a[4];
                const uint32_t rowa = (uint32_t)(m_base + mf * 16 + (lid & 15));
                const uint32_t col = (uint32_t)(ks * 32 + ((lid >> 4) << 4)); // A half
                LDSM_X4(a[0], a[1], a[2], a[3], base + sw128(rowa * 128 + col));
#pragma unroll
                for (int nf = 0; nf < 4; ++nf) {
                    MMA16816(acc[mf][nf][0], acc[mf][nf][1],
                             acc[mf][nf][2], acc[mf][nf][3],
                             a[0], a[1], a[2], a[3], b[0][nf], b[1][nf]);
                }
            }
        }
        __syncthreads();
    }

    // epilogue: certified 3-way classification (mapping validated R12-R14)
    const float thr    = g_thr;
    const float thr_lo = thr - MARG;
    const float thr_hi = thr + MARG;
    const int gi0 = ti * TM + m_base + (lid >> 2);
    const int gj0 = tj * TM + n_base + (lid & 3) * 2;
#pragma unroll
    for (int mf = 0; mf < 4; ++mf)
#pragma unroll
        for (int nf = 0; nf < 4; ++nf)
#pragma unroll
            for (int r = 0; r < 4; ++r) {
                const float v = acc[mf][nf][r];
                if (v >= thr_lo) {
                    const int i = gi0 + mf * 16 + ((r >> 1) << 3);
                    const int j = gj0 + nf * 8 + (r & 1);
                    if (i < j) {
                        const uint32_t pk = ((uint32_t)i << 13) | (uint32_t)j;
                        if (v >= thr_hi) {
                            const int pos = atomicAdd(&g_nedges, 1);
                            if (pos < POOLE) g_edges[pos] = pk;
                        } else {
                            const int pos = atomicAdd(&g_nband, 1);
                            if (pos < BANDC) g_band[pos] = pk;
                        }
                    }
                }
            }
}

// ---------------------------------------------------------------------------
// Kernel 1b: exact fp32 recheck of band pairs (one warp per pair).
// ---------------------------------------------------------------------------
__global__ __launch_bounds__(256) void recheck_kernel(const float* __restrict__ V) {
    const float thr = g_thr;
    int nb = g_nband;
    if (nb > BANDC) nb = BANDC;
    const int gw   = (blockIdx.x * blockDim.x + threadIdx.x) >> 5;
    const int lane = threadIdx.x & 31;
    const int nwarp = (gridDim.x * blockDim.x) >> 5;

    for (int e = gw; e < nb; e += nwarp) {
        const uint32_t p = g_band[e];
        const int i = (int)(p >> 13), j = (int)(p & 8191u);
        const float4* xi = (const float4*)(V + (size_t)i * DD) + lane * 2;
        const float4* xj = (const float4*)(V + (size_t)j * DD) + lane * 2;
        const float4 a0 = xi[0], a1 = xi[1];
        const float4 b0 = xj[0], b1 = xj[1];
        float s = a0.x * b0.x + a0.y * b0.y + a0.z * b0.z + a0.w * b0.w
                + a1.x * b1.x + a1.y * b1.y + a1.z * b1.z + a1.w * b1.w;
#pragma unroll
        for (int o = 16; o; o >>= 1) s += __shfl_xor_sync(0xffffffffu, s, o);
        if (lane == 0 && s >= thr) {
            const int pos = atomicAdd(&g_nedges, 1);
            if (pos < POOLE) g_edges[pos] = p;
        }
    }
}

// ---------------------------------------------------------------------------
// Kernel 2: exact merge (CC -> u64 sort -> segmented leader replay).
// Unchanged from round 14 (validated exact, 52 us).
// ---------------------------------------------------------------------------
__global__ __launch_bounds__(1024) void merge_kernel(float* __restrict__ out) {
    __shared__ unsigned short parent[NV];
    __shared__ uint32_t comp[NV];
    __shared__ uint32_t e32[POOLE];
    __shared__ unsigned long long pool[POOLE];
    __shared__ unsigned short comp_start[NV];
    __shared__ int sE, s_changed;

    const int t = threadIdx.x;
    for (int m = t; m < NV; m += 1024) {
        parent[m] = (unsigned short)m;
        comp[m] = (uint32_t)m;
        comp_start[m] = 0xFFFFu;
    }
    if (t == 0) {
        const int e = g_nedges;
        sE = (e < POOLE) ? e : POOLE;
    }
    __syncthreads();
    const int E = sE;
    for (int e = t; e < POOLE; e += 1024)
        e32[e] = (e < E) ? g_edges[e] : 0xFFFFFFFFu;
    __syncthreads();

    for (int iter = 0; iter < 64; ++iter) {
        if (t == 0) s_changed = 0;
        __syncthreads();
        for (int e = t; e < E; e += 1024) {
            const uint32_t p = e32[e];
            const int i = (int)(p >> 13), j = (int)(p & 8191u);
            const uint32_t a = comp[i], b = comp[j];
            if (a != b) {
                const uint32_t lo = (a < b) ? a : b;
                if (a > lo) atomicMin(&comp[i], lo);
                if (b > lo) atomicMin(&comp[j], lo);
                s_changed = 1;
            }
        }
        __syncthreads();
        if (!s_changed) break;
#pragma unroll
        for (int r = 0; r < 3; ++r) {
            for (int v = t; v < NV; v += 1024)
                atomicMin(&comp[v], comp[comp[v]]);
            __syncthreads();
        }
    }
    __syncthreads();

    for (int e = t; e < POOLE; e += 1024) {
        if (e < E) {
            const uint32_t p = e32[e];
            pool[e] = ((unsigned long long)comp[p >> 13] << 26) | (unsigned long long)p;
        } else {
            pool[e] = ~0ULL;
        }
    }
    __syncthreads();

    for (int k = 2; k <= POOLE; k <<= 1) {
        for (int j = k >> 1; j > 0; j >>= 1) {
            for (int idx = t; idx < POOLE; idx += 1024) {
                const int l = idx ^ j;
                if (l > idx) {
                    const unsigned long long a = pool[idx], b = pool[l];
                    const bool up = ((idx & k) == 0);
                    if ((a > b) == up) { pool[idx] = b; pool[l] = a; }
                }
            }
            __syncthreads();
        }
    }

    for (int e = t; e < E; e += 1024) {
        const uint32_t c = (uint32_t)(pool[e] >> 26);
        if (e == 0 || (uint32_t)(pool[e - 1] >> 26) != c)
            comp_start[c] = (unsigned short)e;
    }
    __syncthreads();

    for (int v = t; v < NV; v += 1024) {
        if (comp[v] == (uint32_t)v && comp_start[v] != 0xFFFFu) {
            int e = comp_start[v];
            while (e < E && (uint32_t)(pool[e] >> 26) == (uint32_t)v) {
                const uint32_t p = (uint32_t)(pool[e] & 0x3FFFFFFull);
                const int i = (int)(p >> 13);
                const int j = (int)(p & 8191u);
                int ri = i;
                while (true) { const int q = parent[ri]; if (q == ri) break; ri = q; }
                int rj = j;
                while (true) { const int q = parent[rj]; if (q == rj) break; rj = q; }
                if (ri != rj) parent[rj] = (unsigned short)ri;
                parent[i] = (unsigned short)ri;
                parent[j] = (unsigned short)ri;
                ++e;
            }
        }
    }
    __syncthreads();

    for (int m = t; m < NV; m += 1024) {
        int r = m;
        while (true) { const int q = parent[r]; if (q == r) break; r = q; }
        out[m] = (float)r;
    }
}

// ---------------------------------------------------------------------------
extern "C" void kernel_launch(void* const* d_in, const int* in_sizes, int n_in,
                              void* d_out, int out_size) {
    int vi = 0;
    for (int i = 1; i < n_in; i++)
        if (in_sizes[i] > in_sizes[vi]) vi = i;
    const float* V = (const float*)d_in[vi];

    const void* cands[3] = {nullptr, nullptr, nullptr};
    int nc = 0;
    for (int i = 0; i < n_in && nc < 3; i++)
        if (i != vi) cands[nc++] = d_in[i];

    float* out = (float*)d_out;

    pick_thr_kernel<<<1, 1>>>(cands[0], cands[1], cands[2]);
    split_kernel<<<(NV * DD + 255) / 256, 256>>>(V);
    simgemm_tc<<<NPAIR, 256>>>();
    recheck_kernel<<<128, 256>>>(V);
    merge_kernel<<<1, 1024>>>(out);
}

// round 16
// speedup vs baseline: 6.5844x; 1.1638x over previous
#include <cuda_runtime.h>
#include <cuda_bf16.h>
#include <cstdint>

#define NV    8192
#define DD    256
#define TM    128
#define NT    64
#define NPAIR (NT * (NT + 1) / 2)   // 2080 upper-tri tiles
#define POOLE 4096
#define BANDC 16384                  // band pool (expected ~700; 20x margin)
#define MARG  0.0045f                // certified bf16 1-term error bound +slack

// Scratch (static device globals — allocation-free)
__device__ uint32_t g_edges[POOLE];  // packed (i<<13)|j, i<j
__device__ int      g_nedges;
__device__ uint32_t g_band[BANDC];   // pairs needing exact recheck
__device__ int      g_nband;
__device__ float    g_thr;
__device__ __nv_bfloat16 g_s0[NV * DD];   // bf16 head of V

// ---------------------------------------------------------------------------
__device__ __forceinline__ uint32_t smem_u32(const void* p) {
    uint32_t a;
    asm("{ .reg .u64 t; cvta.to.shared.u64 t, %1; cvt.u32.u64 %0, t; }"
        : "=r"(a) : "l"(p));
    return a;
}
__device__ __forceinline__ uint32_t sw128(uint32_t off) {
    return off ^ ((off >> 3) & 0x70u);
}

#define LDSM_X4(r0, r1, r2, r3, addr) \
    asm volatile("ldmatrix.sync.aligned.m8n8.x4.shared.b16 {%0,%1,%2,%3}, [%4];" \
                 : "=r"(r0), "=r"(r1), "=r"(r2), "=r"(r3) : "r"(addr))

#define MMA16816(c0, c1, c2, c3, a0, a1, a2, a3, b0, b1) \
    asm volatile("mma.sync.aligned.m16n8k16.row.col.f32.bf16.bf16.f32 " \
                 "{%0,%1,%2,%3}, {%4,%5,%6,%7}, {%8,%9}, {%0,%1,%2,%3};" \
                 : "+f"(c0), "+f"(c1), "+f"(c2), "+f"(c3) \
                 : "r"(a0), "r"(a1), "r"(a2), "r"(a3), "r"(b0), "r"(b1))

#define CP_ASYNC16(dst, src) \
    asm volatile("cp.async.cg.shared.global [%0], [%1], 16;" \
                 :: "r"(dst), "l"(src) : "memory")

// ---------------------------------------------------------------------------
// Kernel B: bf16 head of V + (thread 0) threshold pick & counter reset.
// ---------------------------------------------------------------------------
__global__ __launch_bounds__(256) void split_kernel(const float* __restrict__ V,
                                                    const void* c0, const void* c1,
                                                    const void* c2) {
    const int i = blockIdx.x * blockDim.x + threadIdx.x;
    if (i == 0) {
        float t = 0.25f;
        const void* cands[3] = {c0, c1, c2};
#pragma unroll
        for (int q = 0; q < 3; q++) {
            if (cands[q] != nullptr) {
                const float v = *(const float*)cands[q];
                if (v >= 0.001f && v <= 0.999f) { t = v; break; }
            }
        }
        g_thr = t;
        g_nedges = 0;
        g_nband  = 0;
    }
    if (i < NV * DD) g_s0[i] = __float2bfloat16_rn(V[i]);
}

// ---------------------------------------------------------------------------
// Kernel 1: 1-term bf16 prefilter GEMM, cp.async 3-stage pipeline, BK=32.
// approx >= thr+MARG -> certain edge; [thr-MARG, thr+MARG) -> band; else none.
// Certified: |approx - exact| < 0.0040 < MARG (validated exact in R15).
// ---------------------------------------------------------------------------
#define OFFR(r) ((r) * NT - (r) * ((r) - 1) / 2)

__global__ __launch_bounds__(256, 2) void simgemm_tc() {
    const int x = blockIdx.x;
    int ti = (int)(NT + 0.5f - sqrtf((NT + 0.5f) * (NT + 0.5f) - 2.0f * (float)x));
    if (ti < 0) ti = 0;
    while (OFFR(ti + 1) <= x) ++ti;
    while (OFFR(ti) > x) --ti;
    const int tj = ti + (x - OFFR(ti));

    __shared__ __align__(1024) char sb[3][16384];   // [A0 | B0] per stage

    const int tid = threadIdx.x;
    const int wid = tid >> 5, lid = tid & 31;
    const int m_base = (wid & 1) * 64;
    const int n_base = (wid >> 1) * 32;

    const __nv_bfloat16* Ap = g_s0 + (size_t)ti * TM * DD;
    const __nv_bfloat16* Bp = g_s0 + (size_t)tj * TM * DD;

    uint32_t sbase[3] = { smem_u32(sb[0]), smem_u32(sb[1]), smem_u32(sb[2]) };

    float acc[4][4][4];
#pragma unroll
    for (int mf = 0; mf < 4; mf++)
#pragma unroll
        for (int nf = 0; nf < 4; nf++)
#pragma unroll
            for (int r = 0; r < 4; r++) acc[mf][nf][r] = 0.0f;

#define LOAD_STAGE(stbase, kc)                                                 \
    do {                                                                       \
        _Pragma("unroll")                                                      \
        for (int c = 0; c < 4; ++c) {                                          \
            const int q = c * 256 + tid;                                       \
            const int row = q >> 3, c8 = q & 7;                                \
            const int h = c8 >> 2, c4 = c8 & 3;                                \
            const __nv_bfloat16* src = (h ? Bp : Ap) + (size_t)row * DD        \
                                     + (kc) * 32 + c4 * 8;                     \
            const uint32_t dst = (stbase)                                      \
                               + sw128((uint32_t)(row * 128 + c8 * 16));       \
            CP_ASYNC16(dst, src);                                              \
        }                                                                      \
        asm volatile("cp.async.commit_group;" ::: "memory");                   \
    } while (0)

    LOAD_STAGE(sbase[0], 0);
    LOAD_STAGE(sbase[1], 1);

#pragma unroll 1
    for (int kc = 0; kc < 8; ++kc) {
        if (kc < 7) {
            asm volatile("cp.async.wait_group 1;" ::: "memory");
        } else {
            asm volatile("cp.async.wait_group 0;" ::: "memory");
        }
        __syncthreads();
        if (kc < 6) LOAD_STAGE(sbase[(kc + 2) % 3], kc + 2);

        const uint32_t base = sbase[kc % 3];
#pragma unroll
        for (int ks = 0; ks < 2; ++ks) {
            uint32_t b[2][4];
            {
                const uint32_t rowb = (uint32_t)(n_base + lid);
                const uint32_t col0 = (uint32_t)(64 + ks * 32);   // B half
                LDSM_X4(b[0][0], b[0][1], b[0][2], b[0][3],
                        base + sw128(rowb * 128 + col0));
                LDSM_X4(b[1][0], b[1][1], b[1][2], b[1][3],
                        base + sw128(rowb * 128 + col0 + 16));
            }
#pragma unroll
            for (int mf = 0; mf < 4; ++mf) {
                uint32_t a[4];
                const uint32_t rowa = (uint32_t)(m_base + mf * 16 + (lid & 15));
                const uint32_t col = (uint32_t)(ks * 32 + ((lid >> 4) << 4)); // A half
                LDSM_X4(a[0], a[1], a[2], a[3], base + sw128(rowa * 128 + col));
#pragma unroll
                for (int nf = 0; nf < 4; ++nf) {
                    MMA16816(acc[mf][nf][0], acc[mf][nf][1],
                             acc[mf][nf][2], acc[mf][nf][3],
                             a[0], a[1], a[2], a[3], b[0][nf], b[1][nf]);
                }
            }
        }
    }

    // epilogue: certified 3-way classification (mapping validated R12-R15)
    const float thr    = g_thr;
    const float thr_lo = thr - MARG;
    const float thr_hi = thr + MARG;
    const int gi0 = ti * TM + m_base + (lid >> 2);
    const int gj0 = tj * TM + n_base + (lid & 3) * 2;
#pragma unroll
    for (int mf = 0; mf < 4; ++mf)
#pragma unroll
        for (int nf = 0; nf < 4; ++nf)
#pragma unroll
            for (int r = 0; r < 4; ++r) {
                const float v = acc[mf][nf][r];
                if (v >= thr_lo) {
                    const int i = gi0 + mf * 16 + ((r >> 1) << 3);
                    const int j = gj0 + nf * 8 + (r & 1);
                    if (i < j) {
                        const uint32_t pk = ((uint32_t)i << 13) | (uint32_t)j;
                        if (v >= thr_hi) {
                            const int pos = atomicAdd(&g_nedges, 1);
                            if (pos < POOLE) g_edges[pos] = pk;
                        } else {
                            const int pos = atomicAdd(&g_nband, 1);
                            if (pos < BANDC) g_band[pos] = pk;
                        }
                    }
                }
            }
}

// ---------------------------------------------------------------------------
// Kernel 1b: exact fp32 recheck of band pairs (one warp per pair).
// ---------------------------------------------------------------------------
__global__ __launch_bounds__(256) void recheck_kernel(const float* __restrict__ V) {
    const float thr = g_thr;
    int nb = g_nband;
    if (nb > BANDC) nb = BANDC;
    const int gw   = (blockIdx.x * blockDim.x + threadIdx.x) >> 5;
    const int lane = threadIdx.x & 31;
    const int nwarp = (gridDim.x * blockDim.x) >> 5;

    for (int e = gw; e < nb; e += nwarp) {
        const uint32_t p = g_band[e];
        const int i = (int)(p >> 13), j = (int)(p & 8191u);
        const float4* xi = (const float4*)(V + (size_t)i * DD) + lane * 2;
        const float4* xj = (const float4*)(V + (size_t)j * DD) + lane * 2;
        const float4 a0 = xi[0], a1 = xi[1];
        const float4 b0 = xj[0], b1 = xj[1];
        float s = a0.x * b0.x + a0.y * b0.y + a0.z * b0.z + a0.w * b0.w
                + a1.x * b1.x + a1.y * b1.y + a1.z * b1.z + a1.w * b1.w;
#pragma unroll
        for (int o = 16; o; o >>= 1) s += __shfl_xor_sync(0xffffffffu, s, o);
        if (lane == 0 && s >= thr) {
            const int pos = atomicAdd(&g_nedges, 1);
            if (pos < POOLE) g_edges[pos] = p;
        }
    }
}

// ---------------------------------------------------------------------------
// Kernel 2: exact merge (CC -> u64 sort over pow2ceil(E) -> segmented replay).
// ---------------------------------------------------------------------------
__global__ __launch_bounds__(1024) void merge_kernel(float* __restrict__ out) {
    __shared__ unsigned short parent[NV];
    __shared__ uint32_t comp[NV];
    __shared__ uint32_t e32[POOLE];
    __shared__ unsigned long long pool[POOLE];
    __shared__ unsigned short comp_start[NV];
    __shared__ int sE, s_changed;

    const int t = threadIdx.x;
    for (int m = t; m < NV; m += 1024) {
        parent[m] = (unsigned short)m;
        comp[m] = (uint32_t)m;
        comp_start[m] = 0xFFFFu;
    }
    if (t == 0) {
        const int e = g_nedges;
        sE = (e < POOLE) ? e : POOLE;
    }
    __syncthreads();
    const int E = sE;
    int S = 32;
    while (S < E) S <<= 1;   // dynamic sort size (uniform across threads)

    for (int e = t; e < E; e += 1024) e32[e] = g_edges[e];
    __syncthreads();

    // ---- parallel CC: min-label hooking + pointer jumping
    for (int iter = 0; iter < 64; ++iter) {
        if (t == 0) s_changed = 0;
        __syncthreads();
        for (int e = t; e < E; e += 1024) {
            const uint32_t p = e32[e];
            const int i = (int)(p >> 13), j = (int)(p & 8191u);
            const uint32_t a = comp[i], b = comp[j];
            if (a != b) {
                const uint32_t lo = (a < b) ? a : b;
                if (a > lo) atomicMin(&comp[i], lo);
                if (b > lo) atomicMin(&comp[j], lo);
                s_changed = 1;
            }
        }
        __syncthreads();
        if (!s_changed) break;
#pragma unroll
        for (int r = 0; r < 3; ++r) {
            for (int v = t; v < NV; v += 1024)
                atomicMin(&comp[v], comp[comp[v]]);
            __syncthreads();
        }
    }

    // ---- flatten comp to fixpoint (guarantees comp[comp[v]] == comp[v])
    for (;;) {
        if (t == 0) s_changed = 0;
        __syncthreads();
        for (int v = t; v < NV; v += 1024) {
            const uint32_t c = comp[v];
            const uint32_t cc = comp[c];
            if (cc < c) { comp[v] = cc; s_changed = 1; }
        }
        __syncthreads();
        if (!s_changed) break;
        __syncthreads();
    }

    // ---- build u64 keys (comp<<26)|edge in first S slots; pad with max
    for (int e = t; e < S; e += 1024) {
        if (e < E) {
            const uint32_t p = e32[e];
            pool[e] = ((unsigned long long)comp[p >> 13] << 26) | (unsigned long long)p;
        } else {
            pool[e] = ~0ULL;
        }
    }
    __syncthreads();

    // ---- bitonic sort over S slots (ascending)
    for (int k = 2; k <= S; k <<= 1) {
        for (int j = k >> 1; j > 0; j >>= 1) {
            for (int idx = t; idx < S; idx += 1024) {
                const int l = idx ^ j;
                if (l > idx) {
                    const unsigned long long a = pool[idx], b = pool[l];
                    const bool up = ((idx & k) == 0);
                    if ((a > b) == up) { pool[idx] = b; pool[l] = a; }
                }
            }
            __syncthreads();
        }
    }

    // ---- segment starts per component
    for (int e = t; e < E; e += 1024) {
        const uint32_t c = (uint32_t)(pool[e] >> 26);
        if (e == 0 || (uint32_t)(pool[e - 1] >> 26) != c)
            comp_start[c] = (unsigned short)e;
    }
    __syncthreads();

    // ---- per-component sequential replay (leaders concurrent, segment-local)
    for (int v = t; v < NV; v += 1024) {
        if (comp[v] == (uint32_t)v && comp_start[v] != 0xFFFFu) {
            int e = comp_start[v];
            while (e < E && (uint32_t)(pool[e] >> 26) == (uint32_t)v) {
                const uint32_t p = (uint32_t)(pool[e] & 0x3FFFFFFull);
                const int i = (int)(p >> 13);
                const int j = (int)(p & 8191u);
                int ri = i;
                while (true) { const int q = parent[ri]; if (q == ri) break; ri = q; }
                int rj = j;
                while (true) { const int q = parent[rj]; if (q == rj) break; rj = q; }
                if (ri != rj) parent[rj] = (unsigned short)ri;
                parent[i] = (unsigned short)ri;   // path compression
                parent[j] = (unsigned short)ri;
                ++e;
            }
        }
    }
    __syncthreads();

    // ---- final find + float writeback
    for (int m = t; m < NV; m += 1024) {
        int r = m;
        while (true) { const int q = parent[r]; if (q == r) break; r = q; }
        out[m] = (float)r;
    }
}

// ---------------------------------------------------------------------------
extern "C" void kernel_launch(void* const* d_in, const int* in_sizes, int n_in,
                              void* d_out, int out_size) {
    int vi = 0;
    for (int i = 1; i < n_in; i++)
        if (in_sizes[i] > in_sizes[vi]) vi = i;
    const float* V = (const float*)d_in[vi];

    const void* cands[3] = {nullptr, nullptr, nullptr};
    int nc = 0;
    for (int i = 0; i < n_in && nc < 3; i++)
        if (i != vi) cands[nc++] = d_in[i];

    float* out = (float*)d_out;

    split_kernel<<<(NV * DD + 255) / 256, 256>>>(V, cands[0], cands[1], cands[2]);
    simgemm_tc<<<NPAIR, 256>>>();
    recheck_kernel<<<128, 256>>>(V);
    merge_kernel<<<1, 1024>>>(out);
}

// round 17
// speedup vs baseline: 7.1224x; 1.0817x over previous
#include <cuda_runtime.h>
#include <cuda_bf16.h>
#include <cstdint>

#define NV    8192
#define DD    256
#define TM    128
#define NT    64
#define NPAIR (NT * (NT + 1) / 2)   // 2080 upper-tri tiles
#define POOLE 4096
#define BANDC 16384                  // band pool (expected ~700; 20x margin)
#define MARG  0.0045f                // certified bf16 1-term error bound +slack

// Scratch (static device globals — allocation-free)
__device__ uint32_t g_edges[POOLE];  // packed (i<<13)|j, i<j
__device__ int      g_nedges;
__device__ uint32_t g_band[BANDC];   // pairs needing exact recheck
__device__ int      g_nband;
__device__ float    g_thr;
__device__ __nv_bfloat16 g_s0[NV * DD];   // bf16 head of V

// ---------------------------------------------------------------------------
__device__ __forceinline__ uint32_t smem_u32(const void* p) {
    uint32_t a;
    asm("{ .reg .u64 t; cvta.to.shared.u64 t, %1; cvt.u32.u64 %0, t; }"
        : "=r"(a) : "l"(p));
    return a;
}
__device__ __forceinline__ uint32_t sw128(uint32_t off) {
    return off ^ ((off >> 3) & 0x70u);
}

#define LDSM_X4(r0, r1, r2, r3, addr) \
    asm volatile("ldmatrix.sync.aligned.m8n8.x4.shared.b16 {%0,%1,%2,%3}, [%4];" \
                 : "=r"(r0), "=r"(r1), "=r"(r2), "=r"(r3) : "r"(addr))

#define MMA16816(c0, c1, c2, c3, a0, a1, a2, a3, b0, b1) \
    asm volatile("mma.sync.aligned.m16n8k16.row.col.f32.bf16.bf16.f32 " \
                 "{%0,%1,%2,%3}, {%4,%5,%6,%7}, {%8,%9}, {%0,%1,%2,%3};" \
                 : "+f"(c0), "+f"(c1), "+f"(c2), "+f"(c3) \
                 : "r"(a0), "r"(a1), "r"(a2), "r"(a3), "r"(b0), "r"(b1))

#define CP_ASYNC16(dst, src) \
    asm volatile("cp.async.cg.shared.global [%0], [%1], 16;" \
                 :: "r"(dst), "l"(src) : "memory")

// ---------------------------------------------------------------------------
// Kernel B: bf16 head of V + (thread 0) threshold pick & counter reset.
// ---------------------------------------------------------------------------
__global__ __launch_bounds__(256) void split_kernel(const float* __restrict__ V,
                                                    const void* c0, const void* c1,
                                                    const void* c2) {
    const int i = blockIdx.x * blockDim.x + threadIdx.x;
    if (i == 0) {
        float t = 0.25f;
        const void* cands[3] = {c0, c1, c2};
#pragma unroll
        for (int q = 0; q < 3; q++) {
            if (cands[q] != nullptr) {
                const float v = *(const float*)cands[q];
                if (v >= 0.001f && v <= 0.999f) { t = v; break; }
            }
        }
        g_thr = t;
        g_nedges = 0;
        g_nband  = 0;
    }
    if (i < NV * DD) g_s0[i] = __float2bfloat16_rn(V[i]);
}

// ---------------------------------------------------------------------------
// Kernel 1: 1-term bf16 prefilter GEMM, cp.async 3-stage pipeline, BK=64.
// Per stage: A tile 128x64 bf16 (16 KB) at +0, B tile at +16 KB (32 KB/stage).
// approx >= thr+MARG -> certain edge; [thr-MARG, thr+MARG) -> band; else none.
// Certified: |approx - exact| < 0.0040 < MARG (validated exact in R15/R16).
// ---------------------------------------------------------------------------
#define OFFR(r) ((r) * NT - (r) * ((r) - 1) / 2)
#define STAGE_BYTES 32768

__global__ __launch_bounds__(256, 2) void simgemm_tc() {
    const int x = blockIdx.x;
    int ti = (int)(NT + 0.5f - sqrtf((NT + 0.5f) * (NT + 0.5f) - 2.0f * (float)x));
    if (ti < 0) ti = 0;
    while (OFFR(ti + 1) <= x) ++ti;
    while (OFFR(ti) > x) --ti;
    const int tj = ti + (x - OFFR(ti));

    extern __shared__ __align__(1024) char sb[];   // 3 stages x 32 KB

    const int tid = threadIdx.x;
    const int wid = tid >> 5, lid = tid & 31;
    const int m_base = (wid & 1) * 64;
    const int n_base = (wid >> 1) * 32;

    const __nv_bfloat16* Ap = g_s0 + (size_t)ti * TM * DD;
    const __nv_bfloat16* Bp = g_s0 + (size_t)tj * TM * DD;

    uint32_t sbase[3] = { smem_u32(sb), smem_u32(sb) + STAGE_BYTES,
                          smem_u32(sb) + 2 * STAGE_BYTES };

    float acc[4][4][4];
#pragma unroll
    for (int mf = 0; mf < 4; mf++)
#pragma unroll
        for (int nf = 0; nf < 4; nf++)
#pragma unroll
            for (int r = 0; r < 4; r++) acc[mf][nf][r] = 0.0f;

    // stage loader: 2048 16B chunks / 256 threads = 8 each (A tile then B tile)
#define LOAD_STAGE(stbase, kc)                                                 \
    do {                                                                       \
        _Pragma("unroll")                                                      \
        for (int c = 0; c < 8; ++c) {                                          \
            const int q = c * 256 + tid;                                       \
            const int T = q >> 10, idx = q & 1023;                             \
            const int row = idx >> 3, c8 = idx & 7;                            \
            const __nv_bfloat16* src = (T ? Bp : Ap) + (size_t)row * DD        \
                                     + (kc) * 64 + c8 * 8;                     \
            const uint32_t dst = (stbase) + T * 16384                          \
                               + sw128((uint32_t)(row * 128 + c8 * 16));       \
            CP_ASYNC16(dst, src);                                              \
        }                                                                      \
        asm volatile("cp.async.commit_group;" ::: "memory");                   \
    } while (0)

    LOAD_STAGE(sbase[0], 0);
    LOAD_STAGE(sbase[1], 1);

#pragma unroll 1
    for (int kc = 0; kc < 4; ++kc) {
        if (kc < 3) {
            asm volatile("cp.async.wait_group 1;" ::: "memory");
        } else {
            asm volatile("cp.async.wait_group 0;" ::: "memory");
        }
        __syncthreads();
        if (kc < 2) LOAD_STAGE(sbase[(kc + 2) % 3], kc + 2);

        const uint32_t base = sbase[kc % 3];
#pragma unroll
        for (int ks = 0; ks < 4; ++ks) {
            uint32_t b[2][4];
            {
                const uint32_t rowb = (uint32_t)(n_base + lid);
                const uint32_t col0 = (uint32_t)(ks * 32);
                LDSM_X4(b[0][0], b[0][1], b[0][2], b[0][3],
                        base + 16384 + sw128(rowb * 128 + col0));
                LDSM_X4(b[1][0], b[1][1], b[1][2], b[1][3],
                        base + 16384 + sw128(rowb * 128 + col0 + 16));
            }
#pragma unroll
            for (int mf = 0; mf < 4; ++mf) {
                uint32_t a[4];
                const uint32_t rowa = (uint32_t)(m_base + mf * 16 + (lid & 15));
                const uint32_t col = (uint32_t)(ks * 32 + ((lid >> 4) << 4));
                LDSM_X4(a[0], a[1], a[2], a[3], base + sw128(rowa * 128 + col));
#pragma unroll
                for (int nf = 0; nf < 4; ++nf) {
                    MMA16816(acc[mf][nf][0], acc[mf][nf][1],
                             acc[mf][nf][2], acc[mf][nf][3],
                             a[0], a[1], a[2], a[3], b[0][nf], b[1][nf]);
                }
            }
        }
    }

    // epilogue: certified 3-way classification (mapping validated R12-R16)
    const float thr    = g_thr;
    const float thr_lo = thr - MARG;
    const float thr_hi = thr + MARG;
    const int gi0 = ti * TM + m_base + (lid >> 2);
    const int gj0 = tj * TM + n_base + (lid & 3) * 2;
#pragma unroll
    for (int mf = 0; mf < 4; ++mf)
#pragma unroll
        for (int nf = 0; nf < 4; ++nf)
#pragma unroll
            for (int r = 0; r < 4; ++r) {
                const float v = acc[mf][nf][r];
                if (v >= thr_lo) {
                    const int i = gi0 + mf * 16 + ((r >> 1) << 3);
                    const int j = gj0 + nf * 8 + (r & 1);
                    if (i < j) {
                        const uint32_t pk = ((uint32_t)i << 13) | (uint32_t)j;
                        if (v >= thr_hi) {
                            const int pos = atomicAdd(&g_nedges, 1);
                            if (pos < POOLE) g_edges[pos] = pk;
                        } else {
                            const int pos = atomicAdd(&g_nband, 1);
                            if (pos < BANDC) g_band[pos] = pk;
                        }
                    }
                }
            }
}

// ---------------------------------------------------------------------------
// Kernel 1b: exact fp32 recheck of band pairs (one warp per pair).
// ---------------------------------------------------------------------------
__global__ __launch_bounds__(256) void recheck_kernel(const float* __restrict__ V) {
    const float thr = g_thr;
    int nb = g_nband;
    if (nb > BANDC) nb = BANDC;
    const int gw   = (blockIdx.x * blockDim.x + threadIdx.x) >> 5;
    const int lane = threadIdx.x & 31;
    const int nwarp = (gridDim.x * blockDim.x) >> 5;

    for (int e = gw; e < nb; e += nwarp) {
        const uint32_t p = g_band[e];
        const int i = (int)(p >> 13), j = (int)(p & 8191u);
        const float4* xi = (const float4*)(V + (size_t)i * DD) + lane * 2;
        const float4* xj = (const float4*)(V + (size_t)j * DD) + lane * 2;
        const float4 a0 = xi[0], a1 = xi[1];
        const float4 b0 = xj[0], b1 = xj[1];
        float s = a0.x * b0.x + a0.y * b0.y + a0.z * b0.z + a0.w * b0.w
                + a1.x * b1.x + a1.y * b1.y + a1.z * b1.z + a1.w * b1.w;
#pragma unroll
        for (int o = 16; o; o >>= 1) s += __shfl_xor_sync(0xffffffffu, s, o);
        if (lane == 0 && s >= thr) {
            const int pos = atomicAdd(&g_nedges, 1);
            if (pos < POOLE) g_edges[pos] = p;
        }
    }
}

// ---------------------------------------------------------------------------
// Kernel 2: exact merge (CC -> hybrid bitonic sort -> segmented replay).
// ---------------------------------------------------------------------------
__global__ __launch_bounds__(1024) void merge_kernel(float* __restrict__ out) {
    __shared__ unsigned short parent[NV];
    __shared__ uint32_t comp[NV];
    __shared__ uint32_t e32[POOLE];
    __shared__ unsigned long long pool[POOLE];
    __shared__ unsigned short comp_start[NV];
    __shared__ int sE, s_changed;

    const int t = threadIdx.x;
    for (int m = t; m < NV; m += 1024) {
        parent[m] = (unsigned short)m;
        comp[m] = (uint32_t)m;
        comp_start[m] = 0xFFFFu;
    }
    if (t == 0) {
        const int e = g_nedges;
        sE = (e < POOLE) ? e : POOLE;
    }
    __syncthreads();
    const int E = sE;
    int S = 32;
    while (S < E) S <<= 1;   // dynamic sort size (uniform)

    for (int e = t; e < E; e += 1024) e32[e] = g_edges[e];
    __syncthreads();

    // ---- parallel CC: min-label hooking + pointer jumping
    for (int iter = 0; iter < 64; ++iter) {
        if (t == 0) s_changed = 0;
        __syncthreads();
        for (int e = t; e < E; e += 1024) {
            const uint32_t p = e32[e];
            const int i = (int)(p >> 13), j = (int)(p & 8191u);
            const uint32_t a = comp[i], b = comp[j];
            if (a != b) {
                const uint32_t lo = (a < b) ? a : b;
                if (a > lo) atomicMin(&comp[i], lo);
                if (b > lo) atomicMin(&comp[j], lo);
                s_changed = 1;
            }
        }
        __syncthreads();
        if (!s_changed) break;
#pragma unroll
        for (int r = 0; r < 3; ++r) {
            for (int v = t; v < NV; v += 1024)
                atomicMin(&comp[v], comp[comp[v]]);
            __syncthreads();
        }
    }

    // ---- flatten comp to fixpoint
    for (;;) {
        if (t == 0) s_changed = 0;
        __syncthreads();
        for (int v = t; v < NV; v += 1024) {
            const uint32_t c = comp[v];
            const uint32_t cc = comp[c];
            if (cc < c) { comp[v] = cc; s_changed = 1; }
        }
        __syncthreads();
        if (!s_changed) break;
        __syncthreads();
    }

    // ---- build u64 keys (comp<<26)|edge in first S slots; pad with max
    for (int e = t; e < S; e += 1024) {
        if (e < E) {
            const uint32_t p = e32[e];
            pool[e] = ((unsigned long long)comp[p >> 13] << 26) | (unsigned long long)p;
        } else {
            pool[e] = ~0ULL;
        }
    }
    __syncthreads();

    // ---- bitonic sort over S slots (ascending); hybrid when S <= 1024
    if (S <= 1024) {
        for (int k = 2; k <= S; k <<= 1) {
            int j = k >> 1;
            for (; j >= 32; j >>= 1) {
                for (int idx = t; idx < S; idx += 1024) {
                    const int l = idx ^ j;
                    if (l > idx) {
                        const unsigned long long a = pool[idx], b = pool[l];
                        const bool up = ((idx & k) == 0);
                        if ((a > b) == up) { pool[idx] = b; pool[l] = a; }
                    }
                }
                __syncthreads();
            }
            // register phase: strides < 32 within one warp via shfl
            if (t < S) {
                unsigned long long v = pool[t];
                const bool up = ((t & k) == 0);
                for (; j > 0; j >>= 1) {
                    const unsigned long long w =
                        __shfl_xor_sync(0xffffffffu, v, j);
                    const bool lower = ((t & j) == 0);
                    const bool keepmin = (lower == up);
                    v = keepmin ? (v < w ? v : w) : (v > w ? v : w);
                }
                pool[t] = v;
            }
            __syncthreads();
        }
    } else {
        for (int k = 2; k <= S; k <<= 1) {
            for (int j = k >> 1; j > 0; j >>= 1) {
                for (int idx = t; idx < S; idx += 1024) {
                    const int l = idx ^ j;
                    if (l > idx) {
                        const unsigned long long a = pool[idx], b = pool[l];
                        const bool up = ((idx & k) == 0);
                        if ((a > b) == up) { pool[idx] = b; pool[l] = a; }
                    }
                }
                __syncthreads();
            }
        }
    }

    // ---- segment starts per component
    for (int e = t; e < E; e += 1024) {
        const uint32_t c = (uint32_t)(pool[e] >> 26);
        if (e == 0 || (uint32_t)(pool[e - 1] >> 26) != c)
            comp_start[c] = (unsigned short)e;
    }
    __syncthreads();

    // ---- per-component sequential replay (leaders concurrent, segment-local)
    for (int v = t; v < NV; v += 1024) {
        if (comp[v] == (uint32_t)v && comp_start[v] != 0xFFFFu) {
            int e = comp_start[v];
            while (e < E && (uint32_t)(pool[e] >> 26) == (uint32_t)v) {
                const uint32_t p = (uint32_t)(pool[e] & 0x3FFFFFFull);
                const int i = (int)(p >> 13);
                const int j = (int)(p & 8191u);
                int ri = i;
                while (true) { const int q = parent[ri]; if (q == ri) break; ri = q; }
                int rj = j;
                while (true) { const int q = parent[rj]; if (q == rj) break; rj = q; }
                if (ri != rj) parent[rj] = (unsigned short)ri;
                parent[i] = (unsigned short)ri;   // path compression
                parent[j] = (unsigned short)ri;
                ++e;
            }
        }
    }
    __syncthreads();

    // ---- final find + float writeback
    for (int m = t; m < NV; m += 1024) {
        int r = m;
        while (true) { const int q = parent[r]; if (q == r) break; r = q; }
        out[m] = (float)r;
    }
}

// ---------------------------------------------------------------------------
extern "C" void kernel_launch(void* const* d_in, const int* in_sizes, int n_in,
                              void* d_out, int out_size) {
    int vi = 0;
    for (int i = 1; i < n_in; i++)
        if (in_sizes[i] > in_sizes[vi]) vi = i;
    const float* V = (const float*)d_in[vi];

    const void* cands[3] = {nullptr, nullptr, nullptr};
    int nc = 0;
    for (int i = 0; i < n_in && nc < 3; i++)
        if (i != vi) cands[nc++] = d_in[i];

    float* out = (float*)d_out;

    const int dyn = 3 * STAGE_BYTES;   // 96 KB
    cudaFuncSetAttribute(simgemm_tc, cudaFuncAttributeMaxDynamicSharedMemorySize, dyn);

    split_kernel<<<(NV * DD + 255) / 256, 256>>>(V, cands[0], cands[1], cands[2]);
    simgemm_tc<<<NPAIR, 256, dyn>>>();
    recheck_kernel<<<128, 256>>>(V);
    merge_kernel<<<1, 1024>>>(out);
}